// round 14
// baseline (speedup 1.0000x reference)
#include <cuda_runtime.h>
#include <cstdint>

#define N_NODES 50000
#define N_PAD   50048           // 391 * 128
#define N_EDGES 640000
#define IN_CH   128
#define HID_CH  256
#define K_TOT   256
#define TILE_M  128
#define TILE_N  128
#define N_TILES 391             // ceil(50000/128)
#define CHUNK_K 32
#define N_CHUNKS 8
#define STAGES  3
#define PAD     36              // floats per smem row (16B-aligned, ldmatrix conflict-free)
#define NTHREADS 512

// Scratch (__device__ globals zero-initialized; pad rows never RED'd -> stay 0).
__device__ float g_agg[N_PAD * IN_CH];
__device__ float g_cnt[N_PAD];
__device__ float g_Bt[HID_CH * K_TOT];   // Bt[n][k] = Wcat[k][n], tf32-rounded (RNA)

__device__ __forceinline__ uint32_t f2tf(float f) {
    uint32_t r;
    asm("cvt.rna.tf32.f32 %0, %1;" : "=r"(r) : "f"(f));
    return r;
}
__device__ __forceinline__ uint32_t smem_u32(const void* p) {
    return (uint32_t)__cvta_generic_to_shared(p);
}
__device__ __forceinline__ void cp16(uint32_t dst, const void* src) {
    asm volatile("cp.async.ca.shared.global [%0], [%1], 16;"
                 :: "r"(dst), "l"(src) : "memory");
}
__device__ __forceinline__ void cp16_zfill(uint32_t dst, const void* src, int ok) {
    asm volatile("cp.async.ca.shared.global [%0], [%1], 16, %2;"
                 :: "r"(dst), "l"(src), "r"(ok ? 16 : 0) : "memory");
}
__device__ __forceinline__ void ldsm_x4(uint32_t& r0, uint32_t& r1,
                                        uint32_t& r2, uint32_t& r3, uint32_t addr) {
    asm volatile("ldmatrix.sync.aligned.m8n8.x4.shared.b16 {%0,%1,%2,%3}, [%4];"
                 : "=r"(r0), "=r"(r1), "=r"(r2), "=r"(r3) : "r"(addr));
}
__device__ __forceinline__ void mma_tf32(float* c, const uint32_t* a,
                                         uint32_t b0, uint32_t b1) {
    asm("mma.sync.aligned.m16n8k8.row.col.f32.tf32.tf32.f32 "
        "{%0,%1,%2,%3}, {%4,%5,%6,%7}, {%8,%9}, {%0,%1,%2,%3};"
        : "+f"(c[0]), "+f"(c[1]), "+f"(c[2]), "+f"(c[3])
        : "r"(a[0]), "r"(a[1]), "r"(a[2]), "r"(a[3]), "r"(b0), "r"(b1));
}

// ---------------------------------------------------------------------------
// Kernel 1: prep — zero accumulators + transpose weights. Grid widened to
// 2368 blocks (was store-throughput limited at 592).
// ---------------------------------------------------------------------------
__global__ void prep_kernel(const float* __restrict__ W_l,
                            const float* __restrict__ W_r) {
    int idx = blockIdx.x * blockDim.x + threadIdx.x;
    int stride = gridDim.x * blockDim.x;
    const int total4 = (N_PAD * IN_CH) / 4;
    float4 z = make_float4(0.f, 0.f, 0.f, 0.f);
    for (int i = idx; i < total4; i += stride)
        reinterpret_cast<float4*>(g_agg)[i] = z;
    for (int i = idx; i < N_PAD; i += stride) g_cnt[i] = 0.0f;
    for (int i = idx; i < HID_CH * K_TOT; i += stride) {
        int n = i >> 8, k = i & 255;   // K_TOT = 256
        float v = (k < IN_CH) ? W_l[k * HID_CH + n] : W_r[(k - IN_CH) * HID_CH + n];
        g_Bt[n * K_TOT + k] = __uint_as_float(f2tf(v));
    }
}

// ---------------------------------------------------------------------------
// Kernel 2: scatter — 4-edge unrolled per warp (R13, at L2 RED-op ceiling).
// ---------------------------------------------------------------------------
__global__ void __launch_bounds__(256)
scatter_kernel(const float* __restrict__ x,
               const int* __restrict__ edge_index) {
    const int wid = threadIdx.x >> 5;
    const int lane = threadIdx.x & 31;
    const int base = blockIdx.x * 256;

    #pragma unroll
    for (int it = 0; it < 8; ++it) {
        const int e0 = base + it * 32 + wid * 4;
        int srcs[4], dsts[4];
        float4 v[4];
        #pragma unroll
        for (int j = 0; j < 4; ++j) {
            srcs[j] = edge_index[e0 + j];
            dsts[j] = edge_index[N_EDGES + e0 + j];
        }
        #pragma unroll
        for (int j = 0; j < 4; ++j)
            v[j] = reinterpret_cast<const float4*>(x + (size_t)srcs[j] * IN_CH)[lane];
        #pragma unroll
        for (int j = 0; j < 4; ++j) {
            float* a = g_agg + (size_t)dsts[j] * IN_CH + lane * 4;
            asm volatile("red.global.add.v4.f32 [%0], {%1, %2, %3, %4};"
                         :: "l"(a), "f"(v[j].x), "f"(v[j].y),
                            "f"(v[j].z), "f"(v[j].w) : "memory");
            if (lane == 0) atomicAdd(&g_cnt[dsts[j]], 1.0f);
        }
    }
}

// ---------------------------------------------------------------------------
// Kernel 3: fused tf32 GEMM — 512 threads, 16 warps = 4(M) x 4(N), warp tile
// 32x32 (acc 32 regs). launch_bounds(512,2) -> 32 warps/SM. 3-stage cp.async,
// 1 barrier/chunk (R13-proven ordering). Fragment-scaled inv(cnt) on agg chunks.
// ---------------------------------------------------------------------------
#define OFF_BIAS 0
#define OFF_STAGE 512
#define A_BYTES  (TILE_M * PAD * 4)                 // 18432
#define STAGE_BYTES (2 * A_BYTES)                   // 36864
#define SMEM_BYTES (OFF_STAGE + STAGES * STAGE_BYTES)  // 111104 (x2 CTA = 222KB)

__global__ void __launch_bounds__(NTHREADS, 2)
gemm_kernel(const float* __restrict__ x,
            const float* __restrict__ b_l,
            float* __restrict__ out) {
    extern __shared__ char smem[];
    const int tid = threadIdx.x;
    const int wid = tid >> 5, lid = tid & 31;
    const int lrow = lid >> 2, lane4 = lid & 3;
    const int node0 = blockIdx.x * TILE_M;
    const int nblk0 = blockIdx.y * TILE_N;
    const int m_base = (wid & 3) * 32;   // 4 M-warps
    const int n_base = (wid >> 2) * 32;  // 4 N-warps

    float* bias_s = (float*)(smem + OFF_BIAS);
    if (tid < TILE_N) bias_s[tid] = b_l[nblk0 + tid];

    // Per-thread inv(cnt) for the 4 M-rows this thread's A-fragments cover.
    float inv[2][2];
    #pragma unroll
    for (int mi = 0; mi < 2; ++mi)
        #pragma unroll
        for (int h = 0; h < 2; ++h)
            inv[mi][h] = 1.0f / fmaxf(g_cnt[node0 + m_base + mi * 16 + lrow + h * 8], 1.0f);

    // ldmatrix lane-address components (same mapping as R9/R12/R13).
    const int g = lid >> 3;
    const int rin = lid & 7;
    uint32_t aoff[2];
    #pragma unroll
    for (int mi = 0; mi < 2; ++mi)
        aoff[mi] = ((m_base + mi * 16 + (g & 1) * 8 + rin) * PAD + (g >> 1) * 4) * 4;
    uint32_t boff[2];
    #pragma unroll
    for (int p = 0; p < 2; ++p)
        boff[p] = ((n_base + p * 16 + (g >> 1) * 8 + rin) * PAD + (g & 1) * 4) * 4;

    // cp.async mapping: 1024 granules (16B) per operand per chunk; 2 per thread.
    const uint32_t sbase = smem_u32(smem + OFF_STAGE);
    int rows[2], j4s[2];
    uint32_t sdst[2];
    #pragma unroll
    for (int t = 0; t < 2; ++t) {
        int idx = tid + t * NTHREADS;
        rows[t] = idx >> 3;
        j4s[t] = idx & 7;
        sdst[t] = (uint32_t)(rows[t] * PAD + j4s[t] * 4) * 4;
    }

    auto issue = [&](int c) {
        const uint32_t so = (uint32_t)(c % STAGES) * STAGE_BYTES;
        if (c < 4) {
            const int kc = c * CHUNK_K;
            #pragma unroll
            for (int t = 0; t < 2; ++t)   // A from g_agg (padded, unguarded)
                cp16(sbase + so + sdst[t],
                     g_agg + (size_t)(node0 + rows[t]) * IN_CH + kc + j4s[t] * 4);
        } else {
            const int kc = (c - 4) * CHUNK_K;
            #pragma unroll
            for (int t = 0; t < 2; ++t) { // A from x (zfill past N_NODES)
                int node = node0 + rows[t];
                int ok = node < N_NODES;
                cp16_zfill(sbase + so + sdst[t],
                           x + (size_t)(ok ? node : 0) * IN_CH + kc + j4s[t] * 4, ok);
            }
        }
        const int kb = c * CHUNK_K;
        #pragma unroll
        for (int t = 0; t < 2; ++t)       // B from g_Bt
            cp16(sbase + so + A_BYTES + sdst[t],
                 g_Bt + (size_t)(nblk0 + rows[t]) * K_TOT + kb + j4s[t] * 4);
    };

    float acc[2][4][4];
    #pragma unroll
    for (int mi = 0; mi < 2; ++mi)
        #pragma unroll
        for (int ni = 0; ni < 4; ++ni)
            #pragma unroll
            for (int j = 0; j < 4; ++j) acc[mi][ni][j] = 0.f;

    issue(0); asm volatile("cp.async.commit_group;" ::: "memory");
    issue(1); asm volatile("cp.async.commit_group;" ::: "memory");

    #pragma unroll
    for (int c = 0; c < N_CHUNKS; ++c) {
        asm volatile("cp.async.wait_group 1;" ::: "memory");
        __syncthreads();   // single barrier per chunk (R13-proven ordering)

        if (c + 2 < N_CHUNKS) issue(c + 2);
        asm volatile("cp.async.commit_group;" ::: "memory");

        const uint32_t sAc = sbase + (uint32_t)(c % STAGES) * STAGE_BYTES;
        const uint32_t sBc = sAc + A_BYTES;
        #pragma unroll
        for (int ks = 0; ks < 4; ++ks) {
            const uint32_t kb = ks * 32;
            uint32_t a[2][4];
            ldsm_x4(a[0][0], a[0][1], a[0][2], a[0][3], sAc + aoff[0] + kb);
            ldsm_x4(a[1][0], a[1][1], a[1][2], a[1][3], sAc + aoff[1] + kb);
            if (c < 4) {   // agg chunks: scale fragments by per-row inv(cnt)
                #pragma unroll
                for (int mi = 0; mi < 2; ++mi) {
                    a[mi][0] = __float_as_uint(__uint_as_float(a[mi][0]) * inv[mi][0]);
                    a[mi][1] = __float_as_uint(__uint_as_float(a[mi][1]) * inv[mi][1]);
                    a[mi][2] = __float_as_uint(__uint_as_float(a[mi][2]) * inv[mi][0]);
                    a[mi][3] = __float_as_uint(__uint_as_float(a[mi][3]) * inv[mi][1]);
                }
            }
            #pragma unroll
            for (int p = 0; p < 2; ++p) {
                uint32_t b0, b1, b2, b3;
                ldsm_x4(b0, b1, b2, b3, sBc + boff[p] + kb);
                mma_tf32(acc[0][2 * p],     a[0], b0, b1);
                mma_tf32(acc[1][2 * p],     a[1], b0, b1);
                mma_tf32(acc[0][2 * p + 1], a[0], b2, b3);
                mma_tf32(acc[1][2 * p + 1], a[1], b2, b3);
            }
        }
    }

    // ---- epilogue: bias + store ----
    #pragma unroll
    for (int mi = 0; mi < 2; ++mi) {
        int row = node0 + m_base + mi * 16 + lrow;
        #pragma unroll
        for (int ni = 0; ni < 4; ++ni) {
            int col = n_base + ni * 8 + lane4 * 2;
            float b0 = bias_s[col], b1 = bias_s[col + 1];
            if (row < N_NODES) {
                *reinterpret_cast<float2*>(out + (size_t)row * HID_CH + nblk0 + col) =
                    make_float2(acc[mi][ni][0] + b0, acc[mi][ni][1] + b1);
            }
            if (row + 8 < N_NODES) {
                *reinterpret_cast<float2*>(out + (size_t)(row + 8) * HID_CH + nblk0 + col) =
                    make_float2(acc[mi][ni][2] + b0, acc[mi][ni][3] + b1);
            }
        }
    }
}

// ---------------------------------------------------------------------------
// Launch. Inputs: x f32[50000*128], edge_index i32[2*640000],
// W_l f32[128*256], b_l f32[256], W_r f32[128*256]. Out f32[50000*256].
// ---------------------------------------------------------------------------
extern "C" void kernel_launch(void* const* d_in, const int* in_sizes, int n_in,
                              void* d_out, int out_size) {
    const float* x = (const float*)d_in[0];
    const int* edge_index = (const int*)d_in[1];
    const float* W_l = (const float*)d_in[2];
    const float* b_l = (const float*)d_in[3];
    const float* W_r = (const float*)d_in[4];
    float* out = (float*)d_out;

    cudaFuncSetAttribute(gemm_kernel,
                         cudaFuncAttributeMaxDynamicSharedMemorySize, SMEM_BYTES);

    prep_kernel<<<2368, 256>>>(W_l, W_r);
    scatter_kernel<<<2500, 256>>>(x, edge_index);

    dim3 grid(N_TILES, 2);
    gemm_kernel<<<grid, NTHREADS, SMEM_BYTES>>>(x, b_l, out);
}

// round 15
// speedup vs baseline: 1.1421x; 1.1421x over previous
#include <cuda_runtime.h>
#include <cstdint>

#define N_NODES 50000
#define N_PAD   50048           // 391 * 128
#define N_EDGES 640000
#define IN_CH   128
#define HID_CH  256
#define K_TOT   256
#define TILE_M  128
#define TILE_N  128
#define N_TILES 391             // ceil(50000/128)
#define CHUNK_K 32
#define N_CHUNKS 8
#define STAGES  3
#define PAD     36              // floats per smem row (16B-aligned, ldmatrix conflict-free)

// Scratch (__device__ globals zero-initialized; pad rows never RED'd -> stay 0).
__device__ float g_agg[N_PAD * IN_CH];
__device__ float g_cnt[N_PAD];
__device__ float g_Bt[HID_CH * K_TOT];   // Bt[n][k] = Wcat[k][n], tf32-rounded (RNA)

__device__ __forceinline__ uint32_t f2tf(float f) {
    uint32_t r;
    asm("cvt.rna.tf32.f32 %0, %1;" : "=r"(r) : "f"(f));
    return r;
}
__device__ __forceinline__ uint32_t smem_u32(const void* p) {
    return (uint32_t)__cvta_generic_to_shared(p);
}
// .cg: L2-only, no L1 allocation (A/B tiles have no L1 reuse; keep L1 for ldsm).
__device__ __forceinline__ void cp16(uint32_t dst, const void* src) {
    asm volatile("cp.async.cg.shared.global [%0], [%1], 16;"
                 :: "r"(dst), "l"(src) : "memory");
}
__device__ __forceinline__ void cp16_zfill(uint32_t dst, const void* src, int ok) {
    asm volatile("cp.async.cg.shared.global [%0], [%1], 16, %2;"
                 :: "r"(dst), "l"(src), "r"(ok ? 16 : 0) : "memory");
}
__device__ __forceinline__ void ldsm_x4(uint32_t& r0, uint32_t& r1,
                                        uint32_t& r2, uint32_t& r3, uint32_t addr) {
    asm volatile("ldmatrix.sync.aligned.m8n8.x4.shared.b16 {%0,%1,%2,%3}, [%4];"
                 : "=r"(r0), "=r"(r1), "=r"(r2), "=r"(r3) : "r"(addr));
}
__device__ __forceinline__ void mma_tf32(float* c, const uint32_t* a,
                                         uint32_t b0, uint32_t b1) {
    asm("mma.sync.aligned.m16n8k8.row.col.f32.tf32.tf32.f32 "
        "{%0,%1,%2,%3}, {%4,%5,%6,%7}, {%8,%9}, {%0,%1,%2,%3};"
        : "+f"(c[0]), "+f"(c[1]), "+f"(c[2]), "+f"(c[3])
        : "r"(a[0]), "r"(a[1]), "r"(a[2]), "r"(a[3]), "r"(b0), "r"(b1));
}

// ---------------------------------------------------------------------------
// Kernel 1a: zero accumulators only (must precede scatter).
// ---------------------------------------------------------------------------
__global__ void zero_kernel() {
    int idx = blockIdx.x * blockDim.x + threadIdx.x;
    int stride = gridDim.x * blockDim.x;
    const int total4 = (N_PAD * IN_CH) / 4;
    float4 z = make_float4(0.f, 0.f, 0.f, 0.f);
    for (int i = idx; i < total4; i += stride)
        reinterpret_cast<float4*>(g_agg)[i] = z;
    for (int i = idx; i < N_PAD; i += stride) g_cnt[i] = 0.0f;
}

// ---------------------------------------------------------------------------
// Kernel 1b: transpose weights (independent of scatter -> forked stream).
// ---------------------------------------------------------------------------
__global__ void transpose_kernel(const float* __restrict__ W_l,
                                 const float* __restrict__ W_r) {
    int k = blockIdx.x;
    int n = threadIdx.x;
    float v = (k < IN_CH) ? W_l[k * HID_CH + n] : W_r[(k - IN_CH) * HID_CH + n];
    g_Bt[n * K_TOT + k] = __uint_as_float(f2tf(v));
}

// ---------------------------------------------------------------------------
// Kernel 2: scatter — 4-edge unrolled per warp (R13, at L2 RED-op ceiling).
// ---------------------------------------------------------------------------
__global__ void __launch_bounds__(256)
scatter_kernel(const float* __restrict__ x,
               const int* __restrict__ edge_index) {
    const int wid = threadIdx.x >> 5;
    const int lane = threadIdx.x & 31;
    const int base = blockIdx.x * 256;

    #pragma unroll
    for (int it = 0; it < 8; ++it) {
        const int e0 = base + it * 32 + wid * 4;
        int srcs[4], dsts[4];
        float4 v[4];
        #pragma unroll
        for (int j = 0; j < 4; ++j) {
            srcs[j] = edge_index[e0 + j];
            dsts[j] = edge_index[N_EDGES + e0 + j];
        }
        #pragma unroll
        for (int j = 0; j < 4; ++j)
            v[j] = reinterpret_cast<const float4*>(x + (size_t)srcs[j] * IN_CH)[lane];
        #pragma unroll
        for (int j = 0; j < 4; ++j) {
            float* a = g_agg + (size_t)dsts[j] * IN_CH + lane * 4;
            asm volatile("red.global.add.v4.f32 [%0], {%1, %2, %3, %4};"
                         :: "l"(a), "f"(v[j].x), "f"(v[j].y),
                            "f"(v[j].z), "f"(v[j].w) : "memory");
            if (lane == 0) atomicAdd(&g_cnt[dsts[j]], 1.0f);
        }
    }
}

// ---------------------------------------------------------------------------
// Kernel 3: fused tf32 GEMM (R13 structure verbatim; .cg copies; 1-D grid
// with y-major swizzle). 8 warps = 4(M) x 2(N); warp tile 32x64; 3-stage
// cp.async, 1 barrier/chunk; fragment-scaled inv(cnt) on agg chunks.
// ---------------------------------------------------------------------------
#define OFF_BIAS 0
#define OFF_STAGE 512
#define A_BYTES  (TILE_M * PAD * 4)                 // 18432
#define STAGE_BYTES (2 * A_BYTES)                   // 36864
#define SMEM_BYTES (OFF_STAGE + STAGES * STAGE_BYTES)  // 111104 (x2 CTA = 222KB)

__global__ void __launch_bounds__(256, 2)
gemm_kernel(const float* __restrict__ x,
            const float* __restrict__ b_l,
            float* __restrict__ out) {
    extern __shared__ char smem[];
    const int tid = threadIdx.x;
    const int wid = tid >> 5, lid = tid & 31;
    const int lrow = lid >> 2, lane4 = lid & 3;
    // y-major swizzle: both N-halves of an A-tile adjacent in dispatch order.
    const int node0 = (blockIdx.x >> 1) * TILE_M;
    const int nblk0 = (blockIdx.x & 1) * TILE_N;
    const int m_base = (wid & 3) * 32;
    const int n_base = (wid >> 2) * 64;

    float* bias_s = (float*)(smem + OFF_BIAS);
    if (tid < TILE_N) bias_s[tid] = b_l[nblk0 + tid];

    // Per-thread inv(cnt) for the 4 M-rows this thread's A-fragments cover.
    float inv[2][2];
    #pragma unroll
    for (int mi = 0; mi < 2; ++mi)
        #pragma unroll
        for (int h = 0; h < 2; ++h)
            inv[mi][h] = 1.0f / fmaxf(g_cnt[node0 + m_base + mi * 16 + lrow + h * 8], 1.0f);

    // ldmatrix lane-address components (validated R9/R12/R13).
    const int g = lid >> 3;
    const int rin = lid & 7;
    uint32_t aoff[2];
    #pragma unroll
    for (int mi = 0; mi < 2; ++mi)
        aoff[mi] = ((m_base + mi * 16 + (g & 1) * 8 + rin) * PAD + (g >> 1) * 4) * 4;
    uint32_t boff[4];
    #pragma unroll
    for (int p = 0; p < 4; ++p)
        boff[p] = ((n_base + p * 16 + (g >> 1) * 8 + rin) * PAD + (g & 1) * 4) * 4;

    // cp.async mapping: 1024 granules (16B) per operand per chunk; 4 per thread.
    const uint32_t sbase = smem_u32(smem + OFF_STAGE);
    int rows[4], j4s[4];
    uint32_t sdst[4];
    #pragma unroll
    for (int t = 0; t < 4; ++t) {
        int idx = tid + t * 256;
        rows[t] = idx >> 3;
        j4s[t] = idx & 7;
        sdst[t] = (uint32_t)(rows[t] * PAD + j4s[t] * 4) * 4;
    }

    auto issue = [&](int c) {
        const uint32_t so = (uint32_t)(c % STAGES) * STAGE_BYTES;
        if (c < 4) {
            const int kc = c * CHUNK_K;
            #pragma unroll
            for (int t = 0; t < 4; ++t)   // A from g_agg (padded, unguarded)
                cp16(sbase + so + sdst[t],
                     g_agg + (size_t)(node0 + rows[t]) * IN_CH + kc + j4s[t] * 4);
        } else {
            const int kc = (c - 4) * CHUNK_K;
            #pragma unroll
            for (int t = 0; t < 4; ++t) { // A from x (zfill past N_NODES)
                int node = node0 + rows[t];
                int ok = node < N_NODES;
                cp16_zfill(sbase + so + sdst[t],
                           x + (size_t)(ok ? node : 0) * IN_CH + kc + j4s[t] * 4, ok);
            }
        }
        const int kb = c * CHUNK_K;
        #pragma unroll
        for (int t = 0; t < 4; ++t)       // B from g_Bt
            cp16(sbase + so + A_BYTES + sdst[t],
                 g_Bt + (size_t)(nblk0 + rows[t]) * K_TOT + kb + j4s[t] * 4);
    };

    float acc[2][8][4];
    #pragma unroll
    for (int mi = 0; mi < 2; ++mi)
        #pragma unroll
        for (int ni = 0; ni < 8; ++ni)
            #pragma unroll
            for (int j = 0; j < 4; ++j) acc[mi][ni][j] = 0.f;

    issue(0); asm volatile("cp.async.commit_group;" ::: "memory");
    issue(1); asm volatile("cp.async.commit_group;" ::: "memory");

    #pragma unroll
    for (int c = 0; c < N_CHUNKS; ++c) {
        asm volatile("cp.async.wait_group 1;" ::: "memory");
        __syncthreads();   // single barrier per chunk (R13-proven ordering)

        if (c + 2 < N_CHUNKS) issue(c + 2);
        asm volatile("cp.async.commit_group;" ::: "memory");

        const uint32_t sAc = sbase + (uint32_t)(c % STAGES) * STAGE_BYTES;
        const uint32_t sBc = sAc + A_BYTES;
        #pragma unroll
        for (int ks = 0; ks < 4; ++ks) {
            const uint32_t kb = ks * 32;
            uint32_t a[2][4];
            ldsm_x4(a[0][0], a[0][1], a[0][2], a[0][3], sAc + aoff[0] + kb);
            ldsm_x4(a[1][0], a[1][1], a[1][2], a[1][3], sAc + aoff[1] + kb);
            if (c < 4) {   // agg chunks: scale fragments by per-row inv(cnt)
                #pragma unroll
                for (int mi = 0; mi < 2; ++mi) {
                    a[mi][0] = __float_as_uint(__uint_as_float(a[mi][0]) * inv[mi][0]);
                    a[mi][1] = __float_as_uint(__uint_as_float(a[mi][1]) * inv[mi][1]);
                    a[mi][2] = __float_as_uint(__uint_as_float(a[mi][2]) * inv[mi][0]);
                    a[mi][3] = __float_as_uint(__uint_as_float(a[mi][3]) * inv[mi][1]);
                }
            }
            #pragma unroll
            for (int p = 0; p < 4; ++p) {
                uint32_t b0, b1, b2, b3;
                ldsm_x4(b0, b1, b2, b3, sBc + boff[p] + kb);
                mma_tf32(acc[0][2 * p],     a[0], b0, b1);
                mma_tf32(acc[1][2 * p],     a[1], b0, b1);
                mma_tf32(acc[0][2 * p + 1], a[0], b2, b3);
                mma_tf32(acc[1][2 * p + 1], a[1], b2, b3);
            }
        }
    }

    // ---- epilogue: bias + store ----
    #pragma unroll
    for (int mi = 0; mi < 2; ++mi) {
        int row = node0 + m_base + mi * 16 + lrow;
        #pragma unroll
        for (int ni = 0; ni < 8; ++ni) {
            int col = n_base + ni * 8 + lane4 * 2;
            float b0 = bias_s[col], b1 = bias_s[col + 1];
            if (row < N_NODES) {
                *reinterpret_cast<float2*>(out + (size_t)row * HID_CH + nblk0 + col) =
                    make_float2(acc[mi][ni][0] + b0, acc[mi][ni][1] + b1);
            }
            if (row + 8 < N_NODES) {
                *reinterpret_cast<float2*>(out + (size_t)(row + 8) * HID_CH + nblk0 + col) =
                    make_float2(acc[mi][ni][2] + b0, acc[mi][ni][3] + b1);
            }
        }
    }
}

// ---------------------------------------------------------------------------
// Launch: zero -> fork{scatter || transpose} -> join -> gemm.
// Fork-join pattern capture-validated in R11.
// Inputs: x f32[50000*128], edge_index i32[2*640000],
// W_l f32[128*256], b_l f32[256], W_r f32[128*256]. Out f32[50000*256].
// ---------------------------------------------------------------------------
extern "C" void kernel_launch(void* const* d_in, const int* in_sizes, int n_in,
                              void* d_out, int out_size) {
    const float* x = (const float*)d_in[0];
    const int* edge_index = (const int*)d_in[1];
    const float* W_l = (const float*)d_in[2];
    const float* b_l = (const float*)d_in[3];
    const float* W_r = (const float*)d_in[4];
    float* out = (float*)d_out;

    cudaFuncSetAttribute(gemm_kernel,
                         cudaFuncAttributeMaxDynamicSharedMemorySize, SMEM_BYTES);

    cudaStream_t s2;
    cudaStreamCreateWithFlags(&s2, cudaStreamNonBlocking);
    cudaEvent_t ev_fork, ev_join;
    cudaEventCreateWithFlags(&ev_fork, cudaEventDisableTiming);
    cudaEventCreateWithFlags(&ev_join, cudaEventDisableTiming);

    zero_kernel<<<2368, 256>>>();

    cudaEventRecord(ev_fork, 0);
    cudaStreamWaitEvent(s2, ev_fork, 0);

    scatter_kernel<<<2500, 256>>>(x, edge_index);                 // stream 0
    transpose_kernel<<<K_TOT, HID_CH, 0, s2>>>(W_l, W_r);         // s2 (hidden)

    cudaEventRecord(ev_join, s2);
    cudaStreamWaitEvent(0, ev_join, 0);

    gemm_kernel<<<N_TILES * 2, 256, SMEM_BYTES>>>(x, b_l, out);
}